// round 1
// baseline (speedup 1.0000x reference)
#include <cuda_runtime.h>
#include <cuda_bf16.h>
#include <math.h>

// Problem dims (fixed by the problem definition)
#define BATCH 4
#define C_IN 256
#define HH 48
#define WW 48
#define CE 512
#define NS 16
#define DTR 32
#define L (HH * WW)          // 2304
#define M_TOK (BATCH * L)    // 9216

// ---------------- scratch (device globals; no allocation allowed) ----------
__device__ float g_xn[M_TOK * C_IN];      // layernormed input, token-major
__device__ float g_g[M_TOK * CE];         // u * sigmoid(u)
__device__ float g_gu[M_TOK * CE];        // u * sigmoid(-u)
__device__ float g_v[M_TOK * CE];         // v (pre-conv)
__device__ float g_vs[M_TOK * CE];        // silu(conv(v))
__device__ float g_gate[M_TOK * CE];      // g_vs * g_gu
__device__ float g_dbc[M_TOK * 64];       // [dt(32) | B(16) | C(16)]
__device__ float g_delta[M_TOK * CE];     // softplus(dt @ W_dt^T + b_dt)
__device__ float g_y[M_TOK * CE];         // scan output
__device__ float g_tmp[M_TOK * C_IN];     // pre-transpose final

// ---------------- LayerNorm over C (NCHW input, coalesced via smem) --------
// Block: 256 threads, handles 8 consecutive tokens (hw positions) of one batch.
__global__ void ln_kernel(const float* __restrict__ x,
                          const float* __restrict__ nw,
                          const float* __restrict__ nb,
                          float* __restrict__ xn)
{
    __shared__ float sx[8][260];
    int m0 = blockIdx.x * 8;
    int b = m0 / L;
    int hw0 = m0 % L;

    int to = threadIdx.x & 7;      // token offset in tile
    int cb = threadIdx.x >> 3;     // 0..31
    #pragma unroll
    for (int c = cb; c < C_IN; c += 32)
        sx[to][c] = x[((size_t)(b * C_IN + c)) * L + hw0 + to];
    __syncthreads();

    int wid = threadIdx.x >> 5;    // warp -> token
    int lane = threadIdx.x & 31;
    float s1 = 0.f, s2 = 0.f;
    #pragma unroll
    for (int c = lane; c < C_IN; c += 32) {
        float v = sx[wid][c];
        s1 += v; s2 += v * v;
    }
    #pragma unroll
    for (int o = 16; o; o >>= 1) {
        s1 += __shfl_xor_sync(0xffffffffu, s1, o);
        s2 += __shfl_xor_sync(0xffffffffu, s2, o);
    }
    float mean = s1 * (1.f / C_IN);
    float var  = s2 * (1.f / C_IN) - mean * mean;
    float rstd = rsqrtf(var + 1e-6f);
    size_t mrow = (size_t)(m0 + wid) * C_IN;
    #pragma unroll
    for (int c = lane; c < C_IN; c += 32)
        xn[mrow + c] = (sx[wid][c] - mean) * rstd * nw[c] + nb[c];
}

// ---------------- generic tiled GEMM: O = A[M,K] @ W[N,K]^T + bias ---------
// EPI: 0 plain, 1 = G1 split (u->g/gate_u, v), 2 = softplus
// ALOAD: 0 plain A, 1 fused z = A*A2 + A3
template<int EPI, int ALOAD>
__global__ void gemm_kernel(const float* __restrict__ A, int lda,
                            const float* __restrict__ A2,
                            const float* __restrict__ A3,
                            const float* __restrict__ W,
                            const float* __restrict__ bias,
                            float* __restrict__ O0,
                            float* __restrict__ O1,
                            float* __restrict__ O2,
                            int M, int N, int K)
{
    const int BM = 64, BN = 64, BK = 16;
    __shared__ float As[BK][BM + 4];
    __shared__ float Ws[BK][BN + 4];

    int tid = threadIdx.x;
    int tx = tid & 15;
    int ty = tid >> 4;
    int m0 = blockIdx.y * BM;
    int n0 = blockIdx.x * BN;

    int la_m = tid >> 2;          // 0..63
    int la_k = (tid & 3) << 2;    // 0,4,8,12

    float acc[4][4] = {};

    for (int k0 = 0; k0 < K; k0 += BK) {
        // A tile
        {
            size_t base = (size_t)(m0 + la_m) * lda + k0 + la_k;
            #pragma unroll
            for (int j = 0; j < 4; j++) {
                float a = A[base + j];
                if (ALOAD == 1)
                    a = a * A2[base + j] + A3[base + j];
                As[la_k + j][la_m] = a;
            }
        }
        // W tile (W is [N,K] row-major)
        {
            size_t base = (size_t)(n0 + la_m) * K + k0 + la_k;
            #pragma unroll
            for (int j = 0; j < 4; j++)
                Ws[la_k + j][la_m] = W[base + j];
        }
        __syncthreads();

        #pragma unroll
        for (int kk = 0; kk < BK; kk++) {
            float4 a4 = *(const float4*)&As[kk][ty * 4];
            float4 b4 = *(const float4*)&Ws[kk][tx * 4];
            float ar[4] = {a4.x, a4.y, a4.z, a4.w};
            float br[4] = {b4.x, b4.y, b4.z, b4.w};
            #pragma unroll
            for (int i = 0; i < 4; i++)
                #pragma unroll
                for (int j = 0; j < 4; j++)
                    acc[i][j] += ar[i] * br[j];
        }
        __syncthreads();
    }

    #pragma unroll
    for (int i = 0; i < 4; i++) {
        int m = m0 + ty * 4 + i;
        #pragma unroll
        for (int j = 0; j < 4; j++) {
            int n = n0 + tx * 4 + j;
            float r = acc[i][j] + bias[n];
            if (EPI == 0) {
                O0[(size_t)m * N + n] = r;
            } else if (EPI == 1) {
                if (n < CE) {
                    // u: g = u*sigmoid(u), gate_u = u*sigmoid(-u) = u - g
                    float s = 1.f / (1.f + __expf(-r));
                    float gg = r * s;
                    O0[(size_t)m * CE + n] = gg;
                    O1[(size_t)m * CE + n] = r - gg;
                } else {
                    O2[(size_t)m * CE + (n - CE)] = r;
                }
            } else if (EPI == 2) {
                // softplus
                float sp = (r > 20.f) ? r : log1pf(__expf(r));
                O0[(size_t)m * N + n] = sp;
            }
        }
    }
}

// ---------------- depthwise 3x3 conv (NHWC) + SiLU + gate fuse -------------
__global__ void conv_kernel(const float* __restrict__ v,
                            const float* __restrict__ ker,   // [3][3][1][CE]
                            const float* __restrict__ gu,
                            float* __restrict__ vs,
                            float* __restrict__ gate)
{
    int m = blockIdx.x;                       // token
    int ce = blockIdx.y * 128 + threadIdx.x;
    int b = m / L;
    int hw = m % L;
    int h = hw / WW, w = hw % WW;

    float acc = 0.f;
    #pragma unroll
    for (int kh = 0; kh < 3; kh++) {
        int hh = h + kh - 1;
        if (hh < 0 || hh >= HH) continue;
        #pragma unroll
        for (int kw = 0; kw < 3; kw++) {
            int ww2 = w + kw - 1;
            if (ww2 < 0 || ww2 >= WW) continue;
            int mm = b * L + hh * WW + ww2;
            acc += v[(size_t)mm * CE + ce] * ker[(kh * 3 + kw) * CE + ce];
        }
    }
    float s = 1.f / (1.f + __expf(-acc));
    float vsv = acc * s;
    size_t idx = (size_t)m * CE + ce;
    vs[idx] = vsv;
    gate[idx] = vsv * gu[idx];
}

// ---------------- sequential selective scan --------------------------------
// One thread per (b, c, n). Block = 128 threads = 8 channels x 16 states.
// Grid = (CE/8, BATCH).
__global__ void scan_kernel(const float* __restrict__ delta,
                            const float* __restrict__ vv,
                            const float* __restrict__ dbc,
                            const float* __restrict__ A_log,
                            const float* __restrict__ D,
                            float* __restrict__ y)
{
    int b = blockIdx.y;
    int c = blockIdx.x * 8 + (threadIdx.x >> 4);
    int n = threadIdx.x & 15;

    // A = -exp(A_log); pre-scale by log2(e) so exp(d*A) = exp2(d*An2)
    float An2 = -__expf(A_log[c * NS + n]) * 1.44269504088896f;
    float Dc = D[c];
    float h = 0.f;

    const float* dptr  = delta + (size_t)b * L * CE + c;
    const float* vptr  = vv    + (size_t)b * L * CE + c;
    const float* bcptr = dbc   + (size_t)b * L * 64 + DTR + n;
    float*       yptr  = y     + (size_t)b * L * CE + c;

    #pragma unroll 2
    for (int t = 0; t < L; t++) {
        float d  = __ldg(dptr);
        float v  = __ldg(vptr);
        float bn = __ldg(bcptr);
        float cn = __ldg(bcptr + NS);

        float dA = exp2f(d * An2);
        h = h * dA + (d * v) * bn;
        float yp = h * cn;
        yp += __shfl_xor_sync(0xffffffffu, yp, 8);
        yp += __shfl_xor_sync(0xffffffffu, yp, 4);
        yp += __shfl_xor_sync(0xffffffffu, yp, 2);
        yp += __shfl_xor_sync(0xffffffffu, yp, 1);
        if (n == 0) *yptr = yp + Dc * v;

        dptr += CE; vptr += CE; bcptr += 64; yptr += CE;
    }
}

// ---------------- transpose [M_TOK, C_IN] -> NCHW --------------------------
__global__ void transpose_kernel(const float* __restrict__ in,
                                 float* __restrict__ out)
{
    __shared__ float tile[32][33];
    int m0 = blockIdx.x * 32;
    int n0 = blockIdx.y * 32;
    int tx = threadIdx.x, ty = threadIdx.y;   // (32, 8)

    #pragma unroll
    for (int i = ty; i < 32; i += 8)
        tile[i][tx] = in[(size_t)(m0 + i) * C_IN + n0 + tx];
    __syncthreads();

    int b = m0 / L;
    int hw0 = m0 % L;
    #pragma unroll
    for (int i = ty; i < 32; i += 8)
        out[((size_t)(b * C_IN + n0 + i)) * L + hw0 + tx] = tile[tx][i];
}

// ---------------- launcher --------------------------------------------------
extern "C" void kernel_launch(void* const* d_in, const int* in_sizes, int n_in,
                              void* d_out, int out_size)
{
    const float* x       = (const float*)d_in[0];
    const float* norm_w  = (const float*)d_in[1];
    const float* norm_b  = (const float*)d_in[2];
    const float* w_ex    = (const float*)d_in[3];
    const float* b_ex    = (const float*)d_in[4];
    const float* w_proj  = (const float*)d_in[5];
    const float* b_proj  = (const float*)d_in[6];
    const float* dw_ker  = (const float*)d_in[7];
    const float* A_log   = (const float*)d_in[8];
    const float* D       = (const float*)d_in[9];
    const float* W_xproj = (const float*)d_in[10];
    const float* b_xproj = (const float*)d_in[11];
    const float* W_dt    = (const float*)d_in[12];
    const float* b_dt    = (const float*)d_in[13];
    float* out = (float*)d_out;

    void *p_xn, *p_g, *p_gu, *p_v, *p_vs, *p_gate, *p_dbc, *p_delta, *p_y, *p_tmp;
    cudaGetSymbolAddress(&p_xn, g_xn);
    cudaGetSymbolAddress(&p_g, g_g);
    cudaGetSymbolAddress(&p_gu, g_gu);
    cudaGetSymbolAddress(&p_v, g_v);
    cudaGetSymbolAddress(&p_vs, g_vs);
    cudaGetSymbolAddress(&p_gate, g_gate);
    cudaGetSymbolAddress(&p_dbc, g_dbc);
    cudaGetSymbolAddress(&p_delta, g_delta);
    cudaGetSymbolAddress(&p_y, g_y);
    cudaGetSymbolAddress(&p_tmp, g_tmp);

    float* xn    = (float*)p_xn;
    float* gg    = (float*)p_g;
    float* gu    = (float*)p_gu;
    float* vbuf  = (float*)p_v;
    float* vs    = (float*)p_vs;
    float* gate  = (float*)p_gate;
    float* dbc   = (float*)p_dbc;
    float* delta = (float*)p_delta;
    float* ybuf  = (float*)p_y;
    float* tmp   = (float*)p_tmp;

    // 1) LayerNorm (NCHW -> token-major normalized)
    ln_kernel<<<M_TOK / 8, 256>>>(x, norm_w, norm_b, xn);

    // 2) uv = xn @ w_ex^T + b_ex ; split epilogue -> g, gate_u, v
    gemm_kernel<1, 0><<<dim3((2 * CE) / 64, M_TOK / 64), 256>>>(
        xn, C_IN, nullptr, nullptr, w_ex, b_ex, gg, gu, vbuf,
        M_TOK, 2 * CE, C_IN);

    // 3) depthwise conv + SiLU + gate = vs * gate_u
    conv_kernel<<<dim3(M_TOK, CE / 128), 128>>>(vbuf, dw_ker, gu, vs, gate);

    // 4) dbc = vs @ W_xproj^T + b_xproj
    gemm_kernel<0, 0><<<dim3(64 / 64, M_TOK / 64), 256>>>(
        vs, CE, nullptr, nullptr, W_xproj, b_xproj, dbc, nullptr, nullptr,
        M_TOK, 64, CE);

    // 5) delta = softplus(dt @ W_dt^T + b_dt) ; dt = dbc[:, :32] (lda=64)
    gemm_kernel<2, 0><<<dim3(CE / 64, M_TOK / 64), 256>>>(
        dbc, 64, nullptr, nullptr, W_dt, b_dt, delta, nullptr, nullptr,
        M_TOK, CE, DTR);

    // 6) sequential selective scan -> y
    scan_kernel<<<dim3(CE / 8, BATCH), 128>>>(delta, vs, dbc, A_log, D, ybuf);

    // 7) out_tmp = (y*g + gate) @ w_proj^T + b_proj
    gemm_kernel<0, 1><<<dim3(C_IN / 64, M_TOK / 64), 256>>>(
        ybuf, CE, gg, gate, w_proj, b_proj, tmp, nullptr, nullptr,
        M_TOK, C_IN, CE);

    // 8) transpose [M, C] -> [B, C, H, W]
    transpose_kernel<<<dim3(M_TOK / 32, C_IN / 32), dim3(32, 8)>>>(tmp, out);
}

// round 2
// speedup vs baseline: 2.0873x; 2.0873x over previous
#include <cuda_runtime.h>
#include <cuda_bf16.h>
#include <math.h>

// Problem dims (fixed by the problem definition)
#define BATCH 4
#define C_IN 256
#define HH 48
#define WW 48
#define CE 512
#define NS 16
#define DTR 32
#define L (HH * WW)          // 2304
#define M_TOK (BATCH * L)    // 9216

#define NCH 36               // scan chunks
#define CT 64                // timesteps per chunk (NCH*CT == L)
#define SPLITK 4             // split-K for dbc GEMM

// ---------------- scratch (device globals; no allocation allowed) ----------
__device__ float g_xn[M_TOK * C_IN];
__device__ float g_g[M_TOK * CE];
__device__ float g_gu[M_TOK * CE];
__device__ float g_v[M_TOK * CE];
__device__ float g_vs[M_TOK * CE];
__device__ float g_gate[M_TOK * CE];
__device__ float g_dbc[M_TOK * 64];
__device__ float g_part[SPLITK * M_TOK * 64];
__device__ float g_delta[M_TOK * CE];
__device__ float g_y[M_TOK * CE];
__device__ float g_tmp[M_TOK * C_IN];
__device__ float g_hfin[BATCH * NCH * CE * NS];
__device__ float g_carry[BATCH * NCH * CE * NS];
__device__ float g_S[BATCH * NCH * CE];

// ---------------- LayerNorm over C (NCHW input, coalesced via smem) --------
__global__ void ln_kernel(const float* __restrict__ x,
                          const float* __restrict__ nw,
                          const float* __restrict__ nb,
                          float* __restrict__ xn)
{
    __shared__ float sx[8][260];
    int m0 = blockIdx.x * 8;
    int b = m0 / L;
    int hw0 = m0 % L;

    int to = threadIdx.x & 7;
    int cb = threadIdx.x >> 3;
    #pragma unroll
    for (int c = cb; c < C_IN; c += 32)
        sx[to][c] = x[((size_t)(b * C_IN + c)) * L + hw0 + to];
    __syncthreads();

    int wid = threadIdx.x >> 5;
    int lane = threadIdx.x & 31;
    float s1 = 0.f, s2 = 0.f;
    #pragma unroll
    for (int c = lane; c < C_IN; c += 32) {
        float v = sx[wid][c];
        s1 += v; s2 += v * v;
    }
    #pragma unroll
    for (int o = 16; o; o >>= 1) {
        s1 += __shfl_xor_sync(0xffffffffu, s1, o);
        s2 += __shfl_xor_sync(0xffffffffu, s2, o);
    }
    float mean = s1 * (1.f / C_IN);
    float var  = s2 * (1.f / C_IN) - mean * mean;
    float rstd = rsqrtf(var + 1e-6f);
    size_t mrow = (size_t)(m0 + wid) * C_IN;
    #pragma unroll
    for (int c = lane; c < C_IN; c += 32)
        xn[mrow + c] = (sx[wid][c] - mean) * rstd * nw[c] + nb[c];
}

// ---------------- 128x128 tiled GEMM: O = A[M,K](lda) @ W[N,K]^T + bias ----
// EPI: 0 plain, 1 = uv split (u->g/gate_u, v), 2 = softplus
// ALOAD: 0 plain A, 1 fused z = A*A2 + A3
template<int EPI, int ALOAD>
__global__ __launch_bounds__(256, 2)
void gemm128_kernel(const float* __restrict__ A, int lda,
                    const float* __restrict__ A2,
                    const float* __restrict__ A3,
                    const float* __restrict__ W,
                    const float* __restrict__ bias,
                    float* __restrict__ O0,
                    float* __restrict__ O1,
                    float* __restrict__ O2,
                    int M, int N, int K)
{
    const int BM = 128, BN = 128, BK = 8;
    __shared__ float As[2][BK][BM];
    __shared__ float Bs[2][BK][BN];

    int tid = threadIdx.x;
    int m0 = blockIdx.y * BM, n0 = blockIdx.x * BN;

    int lr = tid >> 1;           // 0..127
    int lk = (tid & 1) << 2;     // 0 or 4

    int tm = (tid >> 4) << 3;    // 0..120
    int tn = (tid & 15) << 3;    // 0..120

    float acc[8][8];
    #pragma unroll
    for (int i = 0; i < 8; i++)
        #pragma unroll
        for (int j = 0; j < 8; j++) acc[i][j] = 0.f;

    const float* Aptr  = A + (size_t)(m0 + lr) * lda + lk;
    const float* Wptr  = W + (size_t)(n0 + lr) * K + lk;
    const float* A2ptr = (ALOAD == 1) ? A2 + (size_t)(m0 + lr) * lda + lk : nullptr;
    const float* A3ptr = (ALOAD == 1) ? A3 + (size_t)(m0 + lr) * lda + lk : nullptr;

    // prologue
    {
        float4 a = *(const float4*)Aptr;
        if (ALOAD == 1) {
            float4 g = *(const float4*)A2ptr;
            float4 q = *(const float4*)A3ptr;
            a.x = a.x * g.x + q.x; a.y = a.y * g.y + q.y;
            a.z = a.z * g.z + q.z; a.w = a.w * g.w + q.w;
        }
        As[0][lk + 0][lr] = a.x; As[0][lk + 1][lr] = a.y;
        As[0][lk + 2][lr] = a.z; As[0][lk + 3][lr] = a.w;
        float4 w4 = *(const float4*)Wptr;
        Bs[0][lk + 0][lr] = w4.x; Bs[0][lk + 1][lr] = w4.y;
        Bs[0][lk + 2][lr] = w4.z; Bs[0][lk + 3][lr] = w4.w;
    }
    __syncthreads();

    int buf = 0;
    for (int k0 = 0; k0 < K; k0 += BK) {
        if (k0 + BK < K) {
            float4 a = *(const float4*)(Aptr + k0 + BK);
            if (ALOAD == 1) {
                float4 g = *(const float4*)(A2ptr + k0 + BK);
                float4 q = *(const float4*)(A3ptr + k0 + BK);
                a.x = a.x * g.x + q.x; a.y = a.y * g.y + q.y;
                a.z = a.z * g.z + q.z; a.w = a.w * g.w + q.w;
            }
            As[buf ^ 1][lk + 0][lr] = a.x; As[buf ^ 1][lk + 1][lr] = a.y;
            As[buf ^ 1][lk + 2][lr] = a.z; As[buf ^ 1][lk + 3][lr] = a.w;
            float4 w4 = *(const float4*)(Wptr + k0 + BK);
            Bs[buf ^ 1][lk + 0][lr] = w4.x; Bs[buf ^ 1][lk + 1][lr] = w4.y;
            Bs[buf ^ 1][lk + 2][lr] = w4.z; Bs[buf ^ 1][lk + 3][lr] = w4.w;
        }
        #pragma unroll
        for (int kk = 0; kk < BK; kk++) {
            float ar[8], br[8];
            *(float4*)&ar[0] = *(const float4*)&As[buf][kk][tm];
            *(float4*)&ar[4] = *(const float4*)&As[buf][kk][tm + 4];
            *(float4*)&br[0] = *(const float4*)&Bs[buf][kk][tn];
            *(float4*)&br[4] = *(const float4*)&Bs[buf][kk][tn + 4];
            #pragma unroll
            for (int i = 0; i < 8; i++)
                #pragma unroll
                for (int j = 0; j < 8; j++)
                    acc[i][j] += ar[i] * br[j];
        }
        __syncthreads();
        buf ^= 1;
    }

    #pragma unroll
    for (int i = 0; i < 8; i++) {
        int m = m0 + tm + i;
        #pragma unroll
        for (int j = 0; j < 8; j++) {
            int n = n0 + tn + j;
            float r = acc[i][j] + __ldg(&bias[n]);
            if (EPI == 0) {
                O0[(size_t)m * N + n] = r;
            } else if (EPI == 1) {
                if (n0 < CE) {
                    float s = 1.f / (1.f + __expf(-r));
                    float gg = r * s;
                    O0[(size_t)m * CE + n] = gg;
                    O1[(size_t)m * CE + n] = r - gg;   // u*sigmoid(-u)
                } else {
                    O2[(size_t)m * CE + (n - CE)] = r;
                }
            } else {
                float sp = (r > 20.f) ? r : log1pf(__expf(r));
                O0[(size_t)m * N + n] = sp;
            }
        }
    }
}

// ---------------- dbc GEMM (N=64), split-K partial ---------------------------
__global__ void gemm_dbc_part(const float* __restrict__ A,   // [M, CE]
                              const float* __restrict__ W,   // [64, CE]
                              float* __restrict__ part)
{
    const int BM = 64, BN = 64, BK = 16;
    const int KS = CE / SPLITK;    // 128
    __shared__ float As[BK][BM + 4];
    __shared__ float Ws[BK][BN + 4];

    int tid = threadIdx.x;
    int tx = tid & 15;
    int ty = tid >> 4;
    int m0 = blockIdx.y * BM;
    int koff = blockIdx.z * KS;

    int la_m = tid >> 2;
    int la_k = (tid & 3) << 2;

    float acc[4][4] = {};

    for (int k0 = koff; k0 < koff + KS; k0 += BK) {
        {
            size_t base = (size_t)(m0 + la_m) * CE + k0 + la_k;
            #pragma unroll
            for (int j = 0; j < 4; j++) As[la_k + j][la_m] = A[base + j];
        }
        {
            size_t base = (size_t)la_m * CE + k0 + la_k;
            #pragma unroll
            for (int j = 0; j < 4; j++) Ws[la_k + j][la_m] = W[base + j];
        }
        __syncthreads();
        #pragma unroll
        for (int kk = 0; kk < BK; kk++) {
            float4 a4 = *(const float4*)&As[kk][ty * 4];
            float4 b4 = *(const float4*)&Ws[kk][tx * 4];
            float ar[4] = {a4.x, a4.y, a4.z, a4.w};
            float br[4] = {b4.x, b4.y, b4.z, b4.w};
            #pragma unroll
            for (int i = 0; i < 4; i++)
                #pragma unroll
                for (int j = 0; j < 4; j++)
                    acc[i][j] += ar[i] * br[j];
        }
        __syncthreads();
    }

    size_t zoff = (size_t)blockIdx.z * M_TOK * 64;
    #pragma unroll
    for (int i = 0; i < 4; i++) {
        int m = m0 + ty * 4 + i;
        #pragma unroll
        for (int j = 0; j < 4; j++)
            part[zoff + (size_t)m * 64 + tx * 4 + j] = acc[i][j];
    }
}

__global__ void dbc_reduce(const float* __restrict__ part,
                           const float* __restrict__ bias,
                           float* __restrict__ dbc)
{
    int idx = blockIdx.x * 256 + threadIdx.x;
    int n = idx & 63;
    const size_t S = (size_t)M_TOK * 64;
    float s = part[idx] + part[idx + S] + part[idx + 2 * S] + part[idx + 3 * S];
    dbc[idx] = s + bias[n];
}

// ---------------- depthwise 3x3 conv (NHWC) + SiLU + gate fuse -------------
__global__ void conv_kernel(const float* __restrict__ v,
                            const float* __restrict__ ker,
                            const float* __restrict__ gu,
                            float* __restrict__ vs,
                            float* __restrict__ gate)
{
    int m = blockIdx.x;
    int ce = blockIdx.y * 128 + threadIdx.x;
    int b = m / L;
    int hw = m % L;
    int h = hw / WW, w = hw % WW;

    float acc = 0.f;
    #pragma unroll
    for (int kh = 0; kh < 3; kh++) {
        int hh = h + kh - 1;
        if (hh < 0 || hh >= HH) continue;
        #pragma unroll
        for (int kw = 0; kw < 3; kw++) {
            int ww2 = w + kw - 1;
            if (ww2 < 0 || ww2 >= WW) continue;
            int mm = b * L + hh * WW + ww2;
            acc += v[(size_t)mm * CE + ce] * ker[(kh * 3 + kw) * CE + ce];
        }
    }
    float s = 1.f / (1.f + __expf(-acc));
    float vsv = acc * s;
    size_t idx = (size_t)m * CE + ce;
    vs[idx] = vsv;
    gate[idx] = vsv * gu[idx];
}

// ---------------- chunked selective scan ------------------------------------
// Phase 1: per-(b,c,chunk) local scan from h=0 -> hfin[16], S = sum(delta)
__global__ __launch_bounds__(128)
void scan_p1(const float* __restrict__ delta,
             const float* __restrict__ vs,
             const float* __restrict__ dbc,
             const float* __restrict__ A_log,
             float* __restrict__ hfin,
             float* __restrict__ Ssum)
{
    __shared__ float sB[CT][NS];
    int b = blockIdx.z;
    int k = blockIdx.y;
    int c = blockIdx.x * 128 + threadIdx.x;
    int t0 = k * CT;

    for (int i = threadIdx.x; i < CT * NS; i += 128) {
        int t = i >> 4, n = i & 15;
        sB[t][n] = dbc[((size_t)(b * L + t0 + t)) * 64 + DTR + n];
    }
    __syncthreads();

    float An2[NS], h[NS];
    #pragma unroll
    for (int n = 0; n < NS; n++) {
        An2[n] = -__expf(A_log[c * NS + n]) * 1.44269504088896f;
        h[n] = 0.f;
    }
    float S = 0.f;
    const float* dp = delta + (size_t)(b * L + t0) * CE + c;
    const float* vp = vs    + (size_t)(b * L + t0) * CE + c;
    #pragma unroll 4
    for (int t = 0; t < CT; t++) {
        float d = __ldg(dp + (size_t)t * CE);
        float v = __ldg(vp + (size_t)t * CE);
        float dv = d * v;
        S += d;
        #pragma unroll
        for (int n = 0; n < NS; n++)
            h[n] = h[n] * exp2f(An2[n] * d) + dv * sB[t][n];
    }
    size_t base = ((size_t)((b * NCH + k) * CE) + c) * NS;
    #pragma unroll
    for (int n = 0; n < NS; n++) hfin[base + n] = h[n];
    Ssum[(size_t)(b * NCH + k) * CE + c] = S;
}

// Phase 2: sequential combine across chunks -> carry-in state per chunk
__global__ void scan_p2(const float* __restrict__ A_log,
                        const float* __restrict__ hfin,
                        const float* __restrict__ Ssum,
                        float* __restrict__ carry)
{
    int idx = blockIdx.x * 256 + threadIdx.x;   // B*CE*NS = 32768
    int n = idx & 15;
    int c = (idx >> 4) & (CE - 1);
    int b = idx >> 13;
    float An2 = -__expf(A_log[c * NS + n]) * 1.44269504088896f;
    float Hc = 0.f;
    #pragma unroll 4
    for (int k = 0; k < NCH; k++) {
        size_t base = ((size_t)((b * NCH + k) * CE) + c) * NS + n;
        carry[base] = Hc;
        float Sk = Ssum[(size_t)(b * NCH + k) * CE + c];
        Hc = Hc * exp2f(An2 * Sk) + hfin[base];
    }
}

// Phase 3: re-run local scan with carry-in, emit y
__global__ __launch_bounds__(128)
void scan_p3(const float* __restrict__ delta,
             const float* __restrict__ vs,
             const float* __restrict__ dbc,
             const float* __restrict__ A_log,
             const float* __restrict__ D,
             const float* __restrict__ carry,
             float* __restrict__ y)
{
    __shared__ float sB[CT][NS];
    __shared__ float sC[CT][NS];
    int b = blockIdx.z;
    int k = blockIdx.y;
    int c = blockIdx.x * 128 + threadIdx.x;
    int t0 = k * CT;

    for (int i = threadIdx.x; i < CT * NS; i += 128) {
        int t = i >> 4, n = i & 15;
        size_t row = ((size_t)(b * L + t0 + t)) * 64;
        sB[t][n] = dbc[row + DTR + n];
        sC[t][n] = dbc[row + DTR + NS + n];
    }
    __syncthreads();

    float An2[NS], h[NS];
    size_t cbase = ((size_t)((b * NCH + k) * CE) + c) * NS;
    #pragma unroll
    for (int n = 0; n < NS; n++) {
        An2[n] = -__expf(A_log[c * NS + n]) * 1.44269504088896f;
        h[n] = carry[cbase + n];
    }
    float Dc = D[c];
    const float* dp = delta + (size_t)(b * L + t0) * CE + c;
    const float* vp = vs    + (size_t)(b * L + t0) * CE + c;
    float*       yp = y     + (size_t)(b * L + t0) * CE + c;
    #pragma unroll 2
    for (int t = 0; t < CT; t++) {
        float d = __ldg(dp + (size_t)t * CE);
        float v = __ldg(vp + (size_t)t * CE);
        float dv = d * v;
        float acc = Dc * v;
        #pragma unroll
        for (int n = 0; n < NS; n++) {
            h[n] = h[n] * exp2f(An2[n] * d) + dv * sB[t][n];
            acc += h[n] * sC[t][n];
        }
        yp[(size_t)t * CE] = acc;
    }
}

// ---------------- transpose [M_TOK, C_IN] -> NCHW --------------------------
__global__ void transpose_kernel(const float* __restrict__ in,
                                 float* __restrict__ out)
{
    __shared__ float tile[32][33];
    int m0 = blockIdx.x * 32;
    int n0 = blockIdx.y * 32;
    int tx = threadIdx.x, ty = threadIdx.y;

    #pragma unroll
    for (int i = ty; i < 32; i += 8)
        tile[i][tx] = in[(size_t)(m0 + i) * C_IN + n0 + tx];
    __syncthreads();

    int b = m0 / L;
    int hw0 = m0 % L;
    #pragma unroll
    for (int i = ty; i < 32; i += 8)
        out[((size_t)(b * C_IN + n0 + i)) * L + hw0 + tx] = tile[tx][i];
}

// ---------------- launcher --------------------------------------------------
extern "C" void kernel_launch(void* const* d_in, const int* in_sizes, int n_in,
                              void* d_out, int out_size)
{
    const float* x       = (const float*)d_in[0];
    const float* norm_w  = (const float*)d_in[1];
    const float* norm_b  = (const float*)d_in[2];
    const float* w_ex    = (const float*)d_in[3];
    const float* b_ex    = (const float*)d_in[4];
    const float* w_proj  = (const float*)d_in[5];
    const float* b_proj  = (const float*)d_in[6];
    const float* dw_ker  = (const float*)d_in[7];
    const float* A_log   = (const float*)d_in[8];
    const float* D       = (const float*)d_in[9];
    const float* W_xproj = (const float*)d_in[10];
    const float* b_xproj = (const float*)d_in[11];
    const float* W_dt    = (const float*)d_in[12];
    const float* b_dt    = (const float*)d_in[13];
    float* out = (float*)d_out;

    void *p;
    float *xn, *gg, *gu, *vbuf, *vsb, *gate, *dbc, *part, *delta, *ybuf, *tmp, *hfin, *carry, *Ssum;
    cudaGetSymbolAddress(&p, g_xn);    xn    = (float*)p;
    cudaGetSymbolAddress(&p, g_g);     gg    = (float*)p;
    cudaGetSymbolAddress(&p, g_gu);    gu    = (float*)p;
    cudaGetSymbolAddress(&p, g_v);     vbuf  = (float*)p;
    cudaGetSymbolAddress(&p, g_vs);    vsb   = (float*)p;
    cudaGetSymbolAddress(&p, g_gate);  gate  = (float*)p;
    cudaGetSymbolAddress(&p, g_dbc);   dbc   = (float*)p;
    cudaGetSymbolAddress(&p, g_part);  part  = (float*)p;
    cudaGetSymbolAddress(&p, g_delta); delta = (float*)p;
    cudaGetSymbolAddress(&p, g_y);     ybuf  = (float*)p;
    cudaGetSymbolAddress(&p, g_tmp);   tmp   = (float*)p;
    cudaGetSymbolAddress(&p, g_hfin);  hfin  = (float*)p;
    cudaGetSymbolAddress(&p, g_carry); carry = (float*)p;
    cudaGetSymbolAddress(&p, g_S);     Ssum  = (float*)p;

    // 1) LayerNorm
    ln_kernel<<<M_TOK / 8, 256>>>(x, norm_w, norm_b, xn);

    // 2) uv = xn @ w_ex^T + b_ex ; epilogue -> g, gate_u, v
    gemm128_kernel<1, 0><<<dim3((2 * CE) / 128, M_TOK / 128), 256>>>(
        xn, C_IN, nullptr, nullptr, w_ex, b_ex, gg, gu, vbuf, M_TOK, 2 * CE, C_IN);

    // 3) depthwise conv + SiLU + gate
    conv_kernel<<<dim3(M_TOK, CE / 128), 128>>>(vbuf, dw_ker, gu, vsb, gate);

    // 4) dbc = vs @ W_xproj^T + b_xproj  (split-K + reduce)
    gemm_dbc_part<<<dim3(1, M_TOK / 64, SPLITK), 256>>>(vsb, W_xproj, part);
    dbc_reduce<<<(M_TOK * 64) / 256, 256>>>(part, b_xproj, dbc);

    // 5) delta = softplus(dt @ W_dt^T + b_dt)
    gemm128_kernel<2, 0><<<dim3(CE / 128, M_TOK / 128), 256>>>(
        dbc, 64, nullptr, nullptr, W_dt, b_dt, delta, nullptr, nullptr, M_TOK, CE, DTR);

    // 6) chunked scan
    scan_p1<<<dim3(CE / 128, NCH, BATCH), 128>>>(delta, vsb, dbc, A_log, hfin, Ssum);
    scan_p2<<<(BATCH * CE * NS) / 256, 256>>>(A_log, hfin, Ssum, carry);
    scan_p3<<<dim3(CE / 128, NCH, BATCH), 128>>>(delta, vsb, dbc, A_log, D, carry, ybuf);

    // 7) out_tmp = (y*g + gate) @ w_proj^T + b_proj
    gemm128_kernel<0, 1><<<dim3(C_IN / 128, M_TOK / 128), 256>>>(
        ybuf, CE, gg, gate, w_proj, b_proj, tmp, nullptr, nullptr, M_TOK, C_IN, CE);

    // 8) transpose to NCHW
    transpose_kernel<<<dim3(M_TOK / 32, C_IN / 32), dim3(32, 8)>>>(tmp, out);
}